// round 3
// baseline (speedup 1.0000x reference)
#include <cuda_runtime.h>
#include <cstdint>

#define TOPK    32
#define NDIM    32768
#define DDIM    128
#define THREADS 512

// candidate bucket capacities (static smem)
#define CAPA 512
#define CAPB 1024
#define CAPC 3072
#define THR_A 3.0f
#define THR_B 2.75f
#define THR_C 2.0f

__device__ __forceinline__ unsigned int ord32(float f) {
    unsigned int b = __float_as_uint(f);
    return b ^ ((b & 0x80000000u) ? 0xFFFFFFFFu : 0x80000000u);
}
__device__ __forceinline__ float unord32(unsigned int u) {
    unsigned int b = (u & 0x80000000u) ? (u ^ 0x80000000u) : ~u;
    return __uint_as_float(b);
}
__device__ __forceinline__ unsigned long long warpMax64(unsigned long long v) {
    #pragma unroll
    for (int off = 16; off > 0; off >>= 1) {
        unsigned long long o = __shfl_down_sync(0xFFFFFFFFu, v, off);
        if (o > v) v = o;
    }
    return v;
}

__global__ __launch_bounds__(THREADS)
void wmp_topk_kernel(const float* __restrict__ Kmat,
                     const float* __restrict__ y,
                     float* __restrict__ out,
                     float* __restrict__ indsOut)
{
    __shared__ unsigned long long cand[CAPA + CAPB + CAPC];
    __shared__ unsigned long long red[THREADS / 32];
    __shared__ unsigned long long topkKey[TOPK];
    __shared__ unsigned long long prevSh;
    __shared__ int cntA, cntB, cntC;
    __shared__ float wgt[TOPK];
    __shared__ int   tidx[TOPK];
    __shared__ float partial[THREADS];

    const int row  = blockIdx.x;
    const int tid  = threadIdx.x;
    const int lane = tid & 31;
    const int wid  = tid >> 5;
    const float* Krow = Kmat + (size_t)row * NDIM;

    if (tid == 0) { cntA = 0; cntB = 0; cntC = 0; }
    __syncthreads();

    // ------------------------------------------------------------------
    // Phase 1: single streaming pass over the row; threshold-filter into
    // three candidate buckets. Key packs value (ordered uint) and ~index
    // so keys are unique and tiebreak == lowest index first (jax top_k).
    // ------------------------------------------------------------------
    const float4* row4 = reinterpret_cast<const float4*>(Krow);
    #pragma unroll
    for (int j = 0; j < NDIM / 4 / THREADS; j++) {   // 16 iterations
        int i4 = tid + j * THREADS;
        float4 v = __ldg(&row4[i4]);
        float f[4] = {v.x, v.y, v.z, v.w};
        #pragma unroll
        for (int c = 0; c < 4; c++) {
            if (f[c] > THR_C) {
                unsigned int idx = (unsigned)(i4 * 4 + c);
                unsigned long long key =
                    ((unsigned long long)ord32(f[c]) << 32) | (0xFFFFFFFFu - idx);
                if (f[c] >= THR_A) {
                    int p = atomicAdd(&cntA, 1);
                    if (p < CAPA) cand[p] = key;
                } else if (f[c] >= THR_B) {
                    int p = atomicAdd(&cntB, 1);
                    if (p < CAPB) cand[CAPA + p] = key;
                } else {
                    int p = atomicAdd(&cntC, 1);
                    if (p < CAPC) cand[CAPA + CAPB + p] = key;
                }
            }
        }
    }
    __syncthreads();

    int cA = cntA, cB = cntB, cC = cntC;
    bool ok = (cA <= CAPA) && (cB <= CAPB) && (cC <= CAPC) &&
              (cA + cB + cC >= TOPK);

    if (ok) {
        // --------------------------------------------------------------
        // Phase 2 (fast path): warp 0 runs 32 rounds of
        // "max key strictly below previous winner" over the smallest
        // bucket prefix guaranteed to contain the top-32.
        // --------------------------------------------------------------
        if (wid == 0) {
            int nA = cA;
            int nB = (cA < TOPK) ? cB : 0;
            int nC = (cA + cB < TOPK) ? cC : 0;
            unsigned long long prev = ~0ull;
            for (int r = 0; r < TOPK; r++) {
                unsigned long long best = 0ull;
                for (int i = lane; i < nA; i += 32) {
                    unsigned long long k = cand[i];
                    if (k < prev && k > best) best = k;
                }
                for (int i = lane; i < nB; i += 32) {
                    unsigned long long k = cand[CAPA + i];
                    if (k < prev && k > best) best = k;
                }
                for (int i = lane; i < nC; i += 32) {
                    unsigned long long k = cand[CAPA + CAPB + i];
                    if (k < prev && k > best) best = k;
                }
                best = warpMax64(best);
                best = __shfl_sync(0xFFFFFFFFu, best, 0);
                if (lane == 0) topkKey[r] = best;
                prev = best;
            }
        }
        __syncthreads();
    } else {
        // --------------------------------------------------------------
        // Phase 2 (exact fallback, never taken on N(0,1) data):
        // 32 block-wide argmax passes over the row (re-read from L2).
        // --------------------------------------------------------------
        if (tid == 0) prevSh = ~0ull;
        __syncthreads();
        for (int r = 0; r < TOPK; r++) {
            unsigned long long prev = prevSh;
            unsigned long long best = 0ull;
            for (int i = tid; i < NDIM; i += THREADS) {
                float fv = __ldg(Krow + i);
                unsigned long long k =
                    ((unsigned long long)ord32(fv) << 32) | (0xFFFFFFFFu - (unsigned)i);
                if (k < prev && k > best) best = k;
            }
            best = warpMax64(best);
            if (lane == 0) red[wid] = best;
            __syncthreads();
            if (wid == 0) {
                unsigned long long b = (lane < THREADS / 32) ? red[lane] : 0ull;
                b = warpMax64(b);
                if (lane == 0) { topkKey[r] = b; prevSh = b; }
            }
            __syncthreads();
        }
    }

    // ------------------------------------------------------------------
    // Phase 3: decode winners, L1-normalize weights (warp 0).
    // ------------------------------------------------------------------
    if (tid < TOPK) {
        unsigned long long k = topkKey[tid];
        float v   = unord32((unsigned)(k >> 32));
        int   idx = (int)(0xFFFFFFFFu - (unsigned)k);
        float a = fabsf(v);
        #pragma unroll
        for (int off = 16; off > 0; off >>= 1)
            a += __shfl_xor_sync(0xFFFFFFFFu, a, off);
        float denom = fmaxf(a, 1e-12f);
        wgt[tid]  = v / denom;
        tidx[tid] = idx;
    }
    __syncthreads();

    // ------------------------------------------------------------------
    // Phase 4: weighted gather of 32 rows of y (coalesced, L2-resident).
    // 512 threads = 128 dims x 4 k-segments of 8.
    // ------------------------------------------------------------------
    int d   = tid & (DDIM - 1);
    int seg = tid >> 7;   // 0..3
    float acc = 0.0f;
    #pragma unroll
    for (int k = 0; k < 8; k++) {
        int kk = seg * 8 + k;
        acc += wgt[kk] * __ldg(&y[(size_t)tidx[kk] * DDIM + d]);
    }
    partial[tid] = acc;
    __syncthreads();
    if (tid < DDIM) {
        float s = partial[tid] + partial[tid + 128] +
                  partial[tid + 256] + partial[tid + 384];
        out[(size_t)row * DDIM + tid] = s;
    }
    // Second output: top-k indices (in descending-value order), as floats.
    if (indsOut != nullptr && tid < TOPK)
        indsOut[(size_t)row * TOPK + tid] = (float)tidx[tid];
}

extern "C" void kernel_launch(void* const* d_in, const int* in_sizes, int n_in,
                              void* d_out, int out_size)
{
    const float* Kmat = (const float*)d_in[0];   // [B, N] float32
    const float* y    = (const float*)d_in[1];   // [N, D] float32
    (void)n_in;

    int Brows = in_sizes[0] / NDIM;
    float* out = (float*)d_out;

    // If the output buffer also carries the indices output, write it after
    // the [B, D] preimage region.
    float* indsOut = nullptr;
    if (out_size >= Brows * DDIM + Brows * TOPK)
        indsOut = out + (size_t)Brows * DDIM;

    wmp_topk_kernel<<<Brows, THREADS>>>(Kmat, y, out, indsOut);
}

// round 6
// speedup vs baseline: 1.8264x; 1.8264x over previous
#include <cuda_runtime.h>
#include <cstdint>

#define TOPK    32
#define NDIM    32768
#define DDIM    128
#define THREADS 512
#define CAP     512
#define THR     2.75f
#define BATCH   8      // independent float4 loads in flight per thread
#define NITER   (NDIM / 4 / THREADS)   // 16 float4 per thread

__device__ __forceinline__ unsigned int ord32(float f) {
    unsigned int b = __float_as_uint(f);
    return b ^ ((b & 0x80000000u) ? 0xFFFFFFFFu : 0x80000000u);
}
__device__ __forceinline__ float unord32(unsigned int u) {
    unsigned int b = (u & 0x80000000u) ? (u ^ 0x80000000u) : ~u;
    return __uint_as_float(b);
}
__device__ __forceinline__ unsigned long long warpMax64(unsigned long long v) {
    #pragma unroll
    for (int off = 16; off > 0; off >>= 1) {
        unsigned long long o = __shfl_down_sync(0xFFFFFFFFu, v, off);
        if (o > v) v = o;
    }
    return v;
}

__global__ __launch_bounds__(THREADS)
void wmp_topk_kernel(const float* __restrict__ Kmat,
                     const float* __restrict__ y,
                     float* __restrict__ out,
                     float* __restrict__ indsOut)
{
    __shared__ unsigned long long cand[CAP];
    __shared__ unsigned long long red[THREADS / 32];
    __shared__ unsigned long long topkKey[TOPK];
    __shared__ unsigned long long prevSh;
    __shared__ int cnt;
    __shared__ float wgt[TOPK];
    __shared__ int   tidx[TOPK];
    __shared__ float partial[THREADS];

    const int row  = blockIdx.x;
    const int tid  = threadIdx.x;
    const int lane = tid & 31;
    const int wid  = tid >> 5;
    const float* Krow = Kmat + (size_t)row * NDIM;

    if (tid == 0) cnt = 0;
    __syncthreads();

    // ------------------------------------------------------------------
    // Phase 1: streaming pass. BATCH independent LDG.128 in flight, then
    // filter with ONE threshold. One combined ballot per float4 group
    // (most groups empty); per-component ballot+aggregated atomic only
    // when the group has a candidate. At most one shared atomic per
    // candidate-bearing warp-component group.
    // ------------------------------------------------------------------
    const float4* row4 = reinterpret_cast<const float4*>(Krow);
    #pragma unroll
    for (int j = 0; j < NITER / BATCH; j++) {          // 2 outer iterations
        float4 v[BATCH];
        #pragma unroll
        for (int u = 0; u < BATCH; u++)
            v[u] = __ldcs(&row4[tid + (j * BATCH + u) * THREADS]);

        #pragma unroll
        for (int u = 0; u < BATCH; u++) {
            float f[4] = {v[u].x, v[u].y, v[u].z, v[u].w};
            int i4 = (tid + (j * BATCH + u) * THREADS) * 4;
            bool any4 = (f[0] > THR) | (f[1] > THR) | (f[2] > THR) | (f[3] > THR);
            if (__ballot_sync(0xFFFFFFFFu, any4)) {
                #pragma unroll
                for (int c = 0; c < 4; c++) {
                    bool pred = f[c] > THR;
                    unsigned mask = __ballot_sync(0xFFFFFFFFu, pred);
                    if (mask) {
                        int leader = __ffs(mask) - 1;
                        int base = 0;
                        if (lane == leader)
                            base = atomicAdd(&cnt, __popc(mask));
                        base = __shfl_sync(0xFFFFFFFFu, base, leader);
                        if (pred) {
                            int slot = base + __popc(mask & ((1u << lane) - 1));
                            if (slot < CAP) {
                                unsigned idx = (unsigned)(i4 + c);
                                cand[slot] =
                                    ((unsigned long long)ord32(f[c]) << 32) |
                                    (0xFFFFFFFFu - idx);
                            }
                        }
                    }
                }
            }
        }
    }
    __syncthreads();

    int c = cnt;
    bool ok = (c >= TOPK) && (c <= CAP);

    if (ok) {
        // --------------------------------------------------------------
        // Phase 2 (fast path): parallel rank selection. Keys are unique,
        // so rank = #{j : cand[j] > cand[t]}; rank < 32 => sorted slot.
        // Broadcast LDS reads, fully parallel across candidates.
        // --------------------------------------------------------------
        for (int t = tid; t < c; t += THREADS) {
            unsigned long long k = cand[t];
            int rank = 0;
            for (int j = 0; j < c; j++)
                rank += (cand[j] > k);
            if (rank < TOPK) topkKey[rank] = k;
        }
        __syncthreads();
    } else {
        // --------------------------------------------------------------
        // Phase 2 (exact fallback, never taken on N(0,1) data):
        // 32 block-wide argmax passes over the row (L2-resident re-read).
        // --------------------------------------------------------------
        if (tid == 0) prevSh = ~0ull;
        __syncthreads();
        for (int r = 0; r < TOPK; r++) {
            unsigned long long prev = prevSh;
            unsigned long long best = 0ull;
            for (int i = tid; i < NDIM; i += THREADS) {
                float fv = __ldg(Krow + i);
                unsigned long long k =
                    ((unsigned long long)ord32(fv) << 32) |
                    (0xFFFFFFFFu - (unsigned)i);
                if (k < prev && k > best) best = k;
            }
            best = warpMax64(best);
            if (lane == 0) red[wid] = best;
            __syncthreads();
            if (wid == 0) {
                unsigned long long b = (lane < THREADS / 32) ? red[lane] : 0ull;
                b = warpMax64(b);
                if (lane == 0) { topkKey[r] = b; prevSh = b; }
            }
            __syncthreads();
        }
    }

    // ------------------------------------------------------------------
    // Phase 3: decode winners, L1-normalize weights (warp 0).
    // ------------------------------------------------------------------
    if (tid < TOPK) {
        unsigned long long k = topkKey[tid];
        float v   = unord32((unsigned)(k >> 32));
        int   idx = (int)(0xFFFFFFFFu - (unsigned)k);
        float a = fabsf(v);
        #pragma unroll
        for (int off = 16; off > 0; off >>= 1)
            a += __shfl_xor_sync(0xFFFFFFFFu, a, off);
        float denom = fmaxf(a, 1e-12f);
        wgt[tid]  = v / denom;
        tidx[tid] = idx;
    }
    __syncthreads();

    // ------------------------------------------------------------------
    // Phase 4: weighted gather of 32 rows of y (coalesced, L2-friendly).
    // 512 threads = 128 dims x 4 k-segments of 8.
    // ------------------------------------------------------------------
    int d   = tid & (DDIM - 1);
    int seg = tid >> 7;   // 0..3
    float acc = 0.0f;
    #pragma unroll
    for (int k = 0; k < 8; k++) {
        int kk = seg * 8 + k;
        acc += wgt[kk] * __ldg(&y[(size_t)tidx[kk] * DDIM + d]);
    }
    partial[tid] = acc;
    __syncthreads();
    if (tid < DDIM) {
        float s = partial[tid] + partial[tid + 128] +
                  partial[tid + 256] + partial[tid + 384];
        out[(size_t)row * DDIM + tid] = s;
    }
    // Second output: top-k indices (descending value order), as floats.
    if (indsOut != nullptr && tid < TOPK)
        indsOut[(size_t)row * TOPK + tid] = (float)tidx[tid];
}

extern "C" void kernel_launch(void* const* d_in, const int* in_sizes, int n_in,
                              void* d_out, int out_size)
{
    const float* Kmat = (const float*)d_in[0];   // [B, N] float32
    const float* y    = (const float*)d_in[1];   // [N, D] float32
    (void)n_in;

    int Brows = in_sizes[0] / NDIM;
    float* out = (float*)d_out;

    float* indsOut = nullptr;
    if (out_size >= Brows * DDIM + Brows * TOPK)
        indsOut = out + (size_t)Brows * DDIM;

    wmp_topk_kernel<<<Brows, THREADS>>>(Kmat, y, out, indsOut);
}